// round 13
// baseline (speedup 1.0000x reference)
#include <cuda_runtime.h>
#include <cuda_bf16.h>
#include <math.h>
#include <cstdint>

// Problem constants
#define BATCH   2
#define SEQ     2048
#define DMODEL  1024
#define NHEADS  16
#define DK      64
#define MROWS   (BATCH * SEQ)      // 4096

// ---------------------------------------------------------------------------
// Scratch (device globals — no allocation allowed)
// ---------------------------------------------------------------------------
// g_q/g_k hold PAIR-PERMUTED d-columns: within each 8-col block, storage
// position 2j holds d=j, 2j+1 holds d=j+4 (j=0..3). g_v/g_ctx are natural.
__device__ float g_q[MROWS * DMODEL];
__device__ float g_k[MROWS * DMODEL];
__device__ float g_v[MROWS * DMODEL];
__device__ float g_ctx[MROWS * DMODEL];
__device__ float r_q[MROWS * DMODEL];     // tf32-rounded inputs
__device__ float r_k[MROWS * DMODEL];
__device__ float r_v[MROWS * DMODEL];
__device__ float r_wq[DMODEL * DMODEL];   // tf32-rounded weights (wq pre-scaled)
__device__ float r_wk[DMODEL * DMODEL];
__device__ float r_wv[DMODEL * DMODEL];
__device__ float r_wo[DMODEL * DMODEL];

__device__ __forceinline__ uint32_t f2tf32(float f) {
    uint32_t u;
    asm("cvt.rna.tf32.f32 %0, %1;" : "=r"(u) : "f"(f));
    return u;
}

// mma.sync m16n8k8 tf32 (layouts validated R4/R5):
//   A: a0=(g,t) a1=(g+8,t) a2=(g,t+4) a3=(g+8,t+4)     [g=lane>>2, t=lane&3]
//   B: b0=(k=t,n=g) b1=(k=t+4,n=g)
//   C: c0=(g,2t) c1=(g,2t+1) c2=(g+8,2t) c3=(g+8,2t+1)
__device__ __forceinline__ void mma_tf32(float* d, const uint32_t* a, const uint32_t* b) {
    asm volatile(
        "mma.sync.aligned.m16n8k8.row.col.f32.tf32.tf32.f32 "
        "{%0,%1,%2,%3}, {%4,%5,%6,%7}, {%8,%9}, {%0,%1,%2,%3};"
        : "+f"(d[0]), "+f"(d[1]), "+f"(d[2]), "+f"(d[3])
        : "r"(a[0]), "r"(a[1]), "r"(a[2]), "r"(a[3]),
          "r"(b[0]), "r"(b[1]));
}

// Fast exp2 for x <= 0, deg-4 minimax + exponent injection (9 ops, no MUFU).
// ti<<23 == n<<23 (1.5*2^23 magic; upper bits shift out), so adding it to
// p's float bits multiplies by 2^n exactly (p in [0.70,1.42], clamp keeps
// the exponent field non-negative).
__device__ __forceinline__ float fexp2(float x) {
    x = fmaxf(x, -126.0f);
    float tt = __fadd_rn(x, 12582912.0f);      // 1.5 * 2^23
    float f  = __fsub_rn(x, __fsub_rn(tt, 12582912.0f));
    float p = 9.6859e-3f;
    p = fmaf(p, f, 5.550411e-2f);
    p = fmaf(p, f, 2.4022651e-1f);
    p = fmaf(p, f, 6.9314718e-1f);
    p = fmaf(p, f, 1.0f);
    return __int_as_float(__float_as_int(p) + (__float_as_int(tt) << 23));
}

// cp.async 16B: global -> shared, bypassing registers.
__device__ __forceinline__ void cp_async16(uint32_t dst_smem, const void* src) {
    asm volatile("cp.async.cg.shared.global [%0], [%1], 16;"
                 :: "r"(dst_smem), "l"(src) : "memory");
}
#define CP_COMMIT() asm volatile("cp.async.commit_group;" ::: "memory")
#define CP_WAIT0()  asm volatile("cp.async.wait_group 0;"  ::: "memory")
#define CP_WAIT1()  asm volatile("cp.async.wait_group 1;"  ::: "memory")

// ---------------------------------------------------------------------------
// Prepass: tf32-round inputs & weights (2 batched launches).
// ---------------------------------------------------------------------------
__global__ void round_acts(const float* __restrict__ q, const float* __restrict__ k,
                           const float* __restrict__ v,
                           float* __restrict__ rq, float* __restrict__ rk,
                           float* __restrict__ rv) {
    const int i = blockIdx.x * 256 + threadIdx.x;
    const float* s;
    float* d;
    if (blockIdx.y == 0)      { s = q; d = rq; }
    else if (blockIdx.y == 1) { s = k; d = rk; }
    else                      { s = v; d = rv; }
    float4 x = ((const float4*)s)[i];
    ((uint4*)d)[i] = make_uint4(f2tf32(x.x), f2tf32(x.y), f2tf32(x.z), f2tf32(x.w));
}

__global__ void round_wts(const float* __restrict__ wq, const float* __restrict__ wk,
                          const float* __restrict__ wv, const float* __restrict__ wo,
                          float* __restrict__ rwq, float* __restrict__ rwk,
                          float* __restrict__ rwv, float* __restrict__ rwo,
                          float qscale) {
    const int i = blockIdx.x * 256 + threadIdx.x;
    const float* s;
    float* d;
    float sc = 1.0f;
    if (blockIdx.y == 0)      { s = wq; d = rwq; sc = qscale; }
    else if (blockIdx.y == 1) { s = wk; d = rwk; }
    else if (blockIdx.y == 2) { s = wv; d = rwv; }
    else                      { s = wo; d = rwo; }
    float4 x = ((const float4*)s)[i];
    ((uint4*)d)[i] = make_uint4(f2tf32(x.x * sc), f2tf32(x.y * sc),
                                f2tf32(x.z * sc), f2tf32(x.w * sc));
}

// ---------------------------------------------------------------------------
// GEMM v2 (mma.sync tf32): C = A[M,K] @ W[N,K]^T + bscale*bias.
// R12 structure (proven): 128 thr, warp tile 64x64, 3-stage cp.async,
// one barrier/iter. NEW: `permute` epilogue flag — Q/K outputs are written
// with pair-permuted d-columns (pos 2j <- d j, 2j+1 <- d j+4 per 8-block)
// so flash can use LDS.64 fragment loads.
// ---------------------------------------------------------------------------
#define GBK  16
#define RSTR 20
#define STAGE_F (128 * RSTR)                 // 2560 floats per operand
#define GEMM_SMEM (3 * 2 * STAGE_F * 4)      // 61440 bytes
#define NKT  (DMODEL / GBK)                  // 64

template <bool RoundOut>
__device__ __forceinline__ void gemm_body(const float* __restrict__ A,
                                          const float* __restrict__ W,
                                          const float* __restrict__ bias,
                                          float* __restrict__ C,
                                          float bscale, bool permute) {
    extern __shared__ uint32_t sg[];

    const int tid  = threadIdx.x;           // 0..127
    const int lane = tid & 31;
    const int wid  = tid >> 5;              // 0..3
    const int g    = lane >> 2;
    const int t    = lane & 3;
    const int wr   = wid >> 1;              // 0..1
    const int wc   = wid & 1;               // 0..1
    const int bx   = blockIdx.x;
    const int by   = blockIdx.y;

    const int lr = tid >> 1;                // 0..63
    const int lc = (tid & 1) * 8;           // 0 or 8
    const float* Ag = A + (size_t)(by * 128 + lr) * DMODEL + lc;
    const float* Wg = W + (size_t)(bx * 128 + lr) * DMODEL + lc;

    const uint32_t sb = (uint32_t)__cvta_generic_to_shared(sg);
    const uint32_t dA0 = sb + (lr * RSTR + lc) * 4;
    const uint32_t dA1 = sb + ((lr + 64) * RSTR + lc) * 4;
    const uint32_t dB0 = dA0 + STAGE_F * 4;
    const uint32_t dB1 = dA1 + STAGE_F * 4;

    #define STAGE_ISSUE(tile, s) do {                                       \
        const float* _a = Ag + (tile) * GBK;                                \
        const float* _w = Wg + (tile) * GBK;                                \
        const uint32_t _o = (uint32_t)(s) * (2 * STAGE_F * 4);              \
        cp_async16(dA0 + _o,      _a);                                      \
        cp_async16(dA0 + _o + 16, _a + 4);                                  \
        cp_async16(dA1 + _o,      _a + 64 * DMODEL);                        \
        cp_async16(dA1 + _o + 16, _a + 64 * DMODEL + 4);                    \
        cp_async16(dB0 + _o,      _w);                                      \
        cp_async16(dB0 + _o + 16, _w + 4);                                  \
        cp_async16(dB1 + _o,      _w + 64 * DMODEL);                        \
        cp_async16(dB1 + _o + 16, _w + 64 * DMODEL + 4);                    \
    } while (0)

    float acc[4][8][4];
    #pragma unroll
    for (int mi = 0; mi < 4; mi++)
        #pragma unroll
        for (int ni = 0; ni < 8; ni++)
            #pragma unroll
            for (int r = 0; r < 4; r++) acc[mi][ni][r] = 0.0f;

    STAGE_ISSUE(0, 0); CP_COMMIT();
    STAGE_ISSUE(1, 1); CP_COMMIT();

    int stg = 0;
    for (int it = 0; it < NKT; it++) {
        CP_WAIT1();
        __syncthreads();

        if (it + 2 < NKT) {
            int s2 = stg + 2; if (s2 >= 3) s2 -= 3;
            STAGE_ISSUE(it + 2, s2);
        }
        CP_COMMIT();

        const uint32_t* As = sg + stg * (2 * STAGE_F);
        const uint32_t* Bs = As + STAGE_F;

        #pragma unroll
        for (int ks = 0; ks < GBK; ks += 8) {
            uint32_t afr[4][4];
            #pragma unroll
            for (int mi = 0; mi < 4; mi++) {
                const int rb = wr * 64 + mi * 16 + g;
                afr[mi][0] = As[rb * RSTR + ks + t];
                afr[mi][1] = As[(rb + 8) * RSTR + ks + t];
                afr[mi][2] = As[rb * RSTR + ks + t + 4];
                afr[mi][3] = As[(rb + 8) * RSTR + ks + t + 4];
            }
            uint32_t bfr[8][2];
            #pragma unroll
            for (int ni = 0; ni < 8; ni++) {
                const int cb = wc * 64 + ni * 8 + g;
                bfr[ni][0] = Bs[cb * RSTR + ks + t];
                bfr[ni][1] = Bs[cb * RSTR + ks + t + 4];
            }
            #pragma unroll
            for (int mi = 0; mi < 4; mi++)
                #pragma unroll
                for (int ni = 0; ni < 8; ni++)
                    mma_tf32(acc[mi][ni], afr[mi], bfr[ni]);
        }

        if (++stg == 3) stg = 0;
    }
    #undef STAGE_ISSUE

    // Permuted column positions for (2t, 2t+1) within an 8-block:
    // j<4 -> pos 2j ; j>=4 -> pos 2(j-4)+1.
    const int pp0 = (t < 2) ? 4 * t : 4 * t - 7;       // for j = 2t
    const int pp1 = (t < 2) ? 4 * t + 2 : 4 * t - 5;   // for j = 2t+1

    #pragma unroll
    for (int mi = 0; mi < 4; mi++) {
        const int r0 = by * 128 + wr * 64 + mi * 16 + g;
        #pragma unroll
        for (int ni = 0; ni < 8; ni++) {
            const int bb8 = bx * 128 + wc * 64 + ni * 8;
            const int cc  = bb8 + 2 * t;
            float2 bv = *(const float2*)(bias + cc);
            const float bsx = bv.x * bscale, bsy = bv.y * bscale;
            float v00 = acc[mi][ni][0] + bsx, v01 = acc[mi][ni][1] + bsy;
            float v10 = acc[mi][ni][2] + bsx, v11 = acc[mi][ni][3] + bsy;
            if (RoundOut) {
                if (permute) {
                    float* C0 = C + (size_t)r0 * DMODEL;
                    float* C1 = C + (size_t)(r0 + 8) * DMODEL;
                    ((uint32_t*)C0)[bb8 + pp0] = f2tf32(v00);
                    ((uint32_t*)C0)[bb8 + pp1] = f2tf32(v01);
                    ((uint32_t*)C1)[bb8 + pp0] = f2tf32(v10);
                    ((uint32_t*)C1)[bb8 + pp1] = f2tf32(v11);
                } else {
                    *(uint2*)(C + (size_t)r0 * DMODEL + cc) =
                        make_uint2(f2tf32(v00), f2tf32(v01));
                    *(uint2*)(C + (size_t)(r0 + 8) * DMODEL + cc) =
                        make_uint2(f2tf32(v10), f2tf32(v11));
                }
            } else {
                *(float2*)(C + (size_t)r0 * DMODEL + cc)       = make_float2(v00, v01);
                *(float2*)(C + (size_t)(r0 + 8) * DMODEL + cc) = make_float2(v10, v11);
            }
        }
    }
}

__global__ __launch_bounds__(128, 2)
void qkv_gemm(const float* q, const float* k, const float* v,
              const float* wq, const float* wk, const float* wv,
              const float* bq, const float* bk, const float* bv,
              float* oq, float* ok, float* ov, float qscale) {
    const float *A, *W, *B;
    float* C;
    float s;
    bool perm;
    if (blockIdx.z == 0)      { A = q; W = wq; B = bq; C = oq; s = qscale; perm = true; }
    else if (blockIdx.z == 1) { A = k; W = wk; B = bk; C = ok; s = 1.0f;  perm = true; }
    else                      { A = v; W = wv; B = bv; C = ov; s = 1.0f;  perm = false; }
    gemm_body<true>(A, W, B, C, s, perm);
}

__global__ __launch_bounds__(128, 2)
void out_gemm(const float* __restrict__ A, const float* __restrict__ W,
              const float* __restrict__ bias, float* __restrict__ C) {
    gemm_body<false>(A, W, bias, C, 1.0f, false);
}

// ---------------------------------------------------------------------------
// Flash attention v3: Q/K arrive PAIR-PERMUTED -> QK^T fragment loads are
// LDS.64 (A 16, B 64 instrs/iter vs 32/128). Deg-4 fexp2. Otherwise the
// R11/R12 structure: cp.async double-buffered K/V, one barrier/iter,
// shuffle-transposed P (P/V indexing is over K's sequence rows — unaffected
// by the d-permutation).
// ---------------------------------------------------------------------------
#define FQT   128
#define FKT   64
#define QSTR  68
#define KSTR  68
#define VSTR  72
#define SM_Q   0
#define SM_K0  (FQT * QSTR)
#define SM_K1  (SM_K0 + FKT * KSTR)
#define SM_V0  (SM_K1 + FKT * KSTR)
#define SM_V1  (SM_V0 + FKT * VSTR)
#define ATT_SMEM ((SM_V1 + FKT * VSTR) * 4)   // 106496 bytes
#define NFT   (SEQ / FKT)

__global__ __launch_bounds__(256, 2)
void flash_attn_mma(const float* __restrict__ Q,
                    const float* __restrict__ Km,
                    const float* __restrict__ Vm,
                    float* __restrict__ ctx) {
    extern __shared__ uint32_t smf[];
    uint32_t* Qs = smf + SM_Q;

    const int tid  = threadIdx.x;
    const int lane = tid & 31;
    const int wid  = tid >> 5;
    const int g    = lane >> 2;
    const int t    = lane & 3;
    const int qb   = wid * 16;
    const int qt   = blockIdx.x;
    const int bh   = blockIdx.y;
    const int b    = bh >> 4;
    const int h    = bh & 15;

    const uint32_t sbase = (uint32_t)__cvta_generic_to_shared(smf);

    // ---- Load Q tile (permuted data copied raw; 16B chunks stay in-block) ----
    {
        const int r  = tid >> 1;
        const int c0 = (tid & 1) * 32;
        const float* Qg = Q + (size_t)(b * SEQ + qt * FQT + r) * DMODEL + h * DK + c0;
        #pragma unroll
        for (int j = 0; j < 8; j++)
            *(uint4*)(Qs + r * QSTR + c0 + j * 4) = *(const uint4*)(Qg + j * 4);
    }

    float oacc[8][4];
    #pragma unroll
    for (int ni = 0; ni < 8; ni++)
        #pragma unroll
        for (int r = 0; r < 4; r++) oacc[ni][r] = 0.0f;
    float m0 = -1e30f, m1 = -1e30f, l0 = 0.0f, l1 = 0.0f;

    const int kvr = tid >> 2;
    const int kvc = (tid & 3) * 16;
    const float* Kg0 = Km + (size_t)(b * SEQ + kvr) * DMODEL + h * DK + kvc;
    const float* Vg0 = Vm + (size_t)(b * SEQ + kvr) * DMODEL + h * DK + kvc;

    const uint32_t dK0 = sbase + (SM_K0 + kvr * KSTR + kvc) * 4;
    const uint32_t dK1 = sbase + (SM_K1 + kvr * KSTR + kvc) * 4;
    const uint32_t dV0 = sbase + (SM_V0 + kvr * VSTR + kvc) * 4;
    const uint32_t dV1 = sbase + (SM_V1 + kvr * VSTR + kvc) * 4;

    #pragma unroll
    for (int j = 0; j < 4; j++) {
        cp_async16(dK0 + j * 16, Kg0 + j * 4);
        cp_async16(dV0 + j * 16, Vg0 + j * 4);
    }
    CP_COMMIT();

    for (int kt = 0; kt < NFT; kt++) {
        const int buf = kt & 1;
        uint32_t* Ks = smf + SM_K0 + buf * (FKT * KSTR);
        uint32_t* Vs = smf + SM_V0 + buf * (FKT * VSTR);

        CP_WAIT0();
        __syncthreads();

        if (kt + 1 < NFT) {
            const float* Kg = Kg0 + (size_t)(kt + 1) * FKT * DMODEL;
            const float* Vg = Vg0 + (size_t)(kt + 1) * FKT * DMODEL;
            const uint32_t dk = buf ? dK0 : dK1;
            const uint32_t dv = buf ? dV0 : dV1;
            #pragma unroll
            for (int j = 0; j < 4; j++) {
                cp_async16(dk + j * 16, Kg + j * 4);
                cp_async16(dv + j * 16, Vg + j * 4);
            }
            CP_COMMIT();
        }

        // ---- S = Q K^T (log2 domain); LDS.64 fragment loads via pair-permute ----
        float s[8][4];
        #pragma unroll
        for (int ni = 0; ni < 8; ni++)
            #pragma unroll
            for (int r = 0; r < 4; r++) s[ni][r] = 0.0f;

        #pragma unroll
        for (int ks = 0; ks < 8; ks++) {
            const int kp = ks * 8 + 2 * t;     // permuted pair position
            uint2 qa0 = *(const uint2*)(Qs + (qb + g    ) * QSTR + kp);
            uint2 qa1 = *(const uint2*)(Qs + (qb + g + 8) * QSTR + kp);
            uint32_t a[4];
            a[0] = qa0.x;   // (row g,   k=t)
            a[1] = qa1.x;   // (row g+8, k=t)
            a[2] = qa0.y;   // (row g,   k=t+4)
            a[3] = qa1.y;   // (row g+8, k=t+4)
            #pragma unroll
            for (int ni = 0; ni < 8; ni++) {
                uint2 kb = *(const uint2*)(Ks + (ni * 8 + g) * KSTR + kp);
                uint32_t bb[2] = { kb.x, kb.y };
                mma_tf32(s[ni], a, bb);
            }
        }

        // ---- Online softmax (reduce over 4-lane t-group) ----
        float tm0 = -1e30f, tm1 = -1e30f;
        #pragma unroll
        for (int ni = 0; ni < 8; ni++) {
            tm0 = fmaxf(tm0, fmaxf(s[ni][0], s[ni][1]));
            tm1 = fmaxf(tm1, fmaxf(s[ni][2], s[ni][3]));
        }
        tm0 = fmaxf(tm0, __shfl_xor_sync(0xffffffffu, tm0, 1));
        tm0 = fmaxf(tm0, __shfl_xor_sync(0xffffffffu, tm0, 2));
        tm1 = fmaxf(tm1, __shfl_xor_sync(0xffffffffu, tm1, 1));
        tm1 = fmaxf(tm1, __shfl_xor_sync(0xffffffffu, tm1, 2));

        const float mn0 = fmaxf(m0, tm0);
        const float mn1 = fmaxf(m1, tm1);
        const float c0 = fexp2(m0 - mn0);
        const float c1 = fexp2(m1 - mn1);
        m0 = mn0; m1 = mn1;

        float rs0 = 0.0f, rs1 = 0.0f;
        uint32_t ps[8][4];
        #pragma unroll
        for (int ni = 0; ni < 8; ni++) {
            float p0 = fexp2(s[ni][0] - mn0);
            float p1 = fexp2(s[ni][1] - mn0);
            float p2 = fexp2(s[ni][2] - mn1);
            float p3 = fexp2(s[ni][3] - mn1);
            rs0 += p0 + p1;
            rs1 += p2 + p3;
            ps[ni][0] = f2tf32(p0);
            ps[ni][1] = f2tf32(p1);
            ps[ni][2] = f2tf32(p2);
            ps[ni][3] = f2tf32(p3);
        }
        rs0 += __shfl_xor_sync(0xffffffffu, rs0, 1);
        rs0 += __shfl_xor_sync(0xffffffffu, rs0, 2);
        rs1 += __shfl_xor_sync(0xffffffffu, rs1, 1);
        rs1 += __shfl_xor_sync(0xffffffffu, rs1, 2);
        l0 = l0 * c0 + rs0;
        l1 = l1 * c1 + rs1;

        #pragma unroll
        for (int ni = 0; ni < 8; ni++) {
            oacc[ni][0] *= c0; oacc[ni][1] *= c0;
            oacc[ni][2] *= c1; oacc[ni][3] *= c1;
        }

        // ---- O += P V (shuffle-transposed P; j-index unpermuted) ----
        const int srcA = (g << 2) | (t >> 1);
        const int srcB = srcA + 2;
        const bool odd = (t & 1) != 0;
        #pragma unroll
        for (int ks = 0; ks < 8; ks++) {
            uint32_t x0 = __shfl_sync(0xffffffffu, ps[ks][0], srcA);
            uint32_t x1 = __shfl_sync(0xffffffffu, ps[ks][1], srcA);
            uint32_t x2 = __shfl_sync(0xffffffffu, ps[ks][2], srcA);
            uint32_t x3 = __shfl_sync(0xffffffffu, ps[ks][3], srcA);
            uint32_t y0 = __shfl_sync(0xffffffffu, ps[ks][0], srcB);
            uint32_t y1 = __shfl_sync(0xffffffffu, ps[ks][1], srcB);
            uint32_t y2 = __shfl_sync(0xffffffffu, ps[ks][2], srcB);
            uint32_t y3 = __shfl_sync(0xffffffffu, ps[ks][3], srcB);
            uint32_t a[4];
            a[0] = odd ? x1 : x0;
            a[1] = odd ? x3 : x2;
            a[2] = odd ? y1 : y0;
            a[3] = odd ? y3 : y2;
            #pragma unroll
            for (int ni = 0; ni < 8; ni++) {
                uint32_t bb[2];
                bb[0] = Vs[(ks * 8 + t    ) * VSTR + ni * 8 + g];
                bb[1] = Vs[(ks * 8 + t + 4) * VSTR + ni * 8 + g];
                mma_tf32(oacc[ni], a, bb);
            }
        }
    }

    // ---- Normalize, round (consumed by out_gemm MMA), write ctx ----
    const float inv0 = 1.0f / l0;
    const float inv1 = 1.0f / l1;
    const int r0 = b * SEQ + qt * FQT + qb + g;
    #pragma unroll
    for (int ni = 0; ni < 8; ni++) {
        const int cc = h * DK + ni * 8 + 2 * t;
        *(uint2*)(ctx + (size_t)r0 * DMODEL + cc) =
            make_uint2(f2tf32(oacc[ni][0] * inv0), f2tf32(oacc[ni][1] * inv0));
        *(uint2*)(ctx + (size_t)(r0 + 8) * DMODEL + cc) =
            make_uint2(f2tf32(oacc[ni][2] * inv1), f2tf32(oacc[ni][3] * inv1));
    }
}

// ---------------------------------------------------------------------------
// Launch
// ---------------------------------------------------------------------------
extern "C" void kernel_launch(void* const* d_in, const int* in_sizes, int n_in,
                              void* d_out, int out_size) {
    const float* q   = (const float*)d_in[0];
    const float* k   = (const float*)d_in[1];
    const float* v   = (const float*)d_in[2];
    const float* w_q = (const float*)d_in[3];
    const float* w_k = (const float*)d_in[4];
    const float* w_v = (const float*)d_in[5];
    const float* w_o = (const float*)d_in[6];
    const float* b_q = (const float*)d_in[7];
    const float* b_k = (const float*)d_in[8];
    const float* b_v = (const float*)d_in[9];
    const float* b_o = (const float*)d_in[10];
    float* out = (float*)d_out;

    float *gq, *gk, *gv, *gctx;
    float *rq, *rk, *rv, *rwq, *rwk, *rwv, *rwo;
    cudaGetSymbolAddress((void**)&gq,   g_q);
    cudaGetSymbolAddress((void**)&gk,   g_k);
    cudaGetSymbolAddress((void**)&gv,   g_v);
    cudaGetSymbolAddress((void**)&gctx, g_ctx);
    cudaGetSymbolAddress((void**)&rq,   r_q);
    cudaGetSymbolAddress((void**)&rk,   r_k);
    cudaGetSymbolAddress((void**)&rv,   r_v);
    cudaGetSymbolAddress((void**)&rwq,  r_wq);
    cudaGetSymbolAddress((void**)&rwk,  r_wk);
    cudaGetSymbolAddress((void**)&rwv,  r_wv);
    cudaGetSymbolAddress((void**)&rwo,  r_wo);

    cudaFuncSetAttribute(flash_attn_mma, cudaFuncAttributeMaxDynamicSharedMemorySize, ATT_SMEM);
    cudaFuncSetAttribute(qkv_gemm, cudaFuncAttributeMaxDynamicSharedMemorySize, GEMM_SMEM);
    cudaFuncSetAttribute(out_gemm, cudaFuncAttributeMaxDynamicSharedMemorySize, GEMM_SMEM);

    const float SCLL2E = 0.125f * 1.44269504088896f;

    dim3 ga(MROWS * DMODEL / 4 / 256, 3);   // (4096, 3)
    round_acts<<<ga, 256>>>(q, k, v, rq, rk, rv);
    dim3 gw(DMODEL * DMODEL / 4 / 256, 4);  // (1024, 4)
    round_wts<<<gw, 256>>>(w_q, w_k, w_v, w_o, rwq, rwk, rwv, rwo, SCLL2E);

    dim3 gqkv(DMODEL / 128, MROWS / 128, 3);  // (8, 32, 3)
    qkv_gemm<<<gqkv, 128, GEMM_SMEM>>>(rq, rk, rv, rwq, rwk, rwv,
                                       b_q, b_k, b_v, gq, gk, gv, SCLL2E);

    dim3 ag(SEQ / FQT, BATCH * NHEADS);       // (16, 32)
    flash_attn_mma<<<ag, 256, ATT_SMEM>>>(gq, gk, gv, gctx);

    dim3 gg(DMODEL / 128, MROWS / 128);       // (8, 32)
    out_gemm<<<gg, 128, GEMM_SMEM>>>(gctx, rwo, b_o, out);
}

// round 14
// speedup vs baseline: 1.0775x; 1.0775x over previous
#include <cuda_runtime.h>
#include <cuda_bf16.h>
#include <math.h>
#include <cstdint>

// Problem constants
#define BATCH   2
#define SEQ     2048
#define DMODEL  1024
#define NHEADS  16
#define DK      64
#define MROWS   (BATCH * SEQ)      // 4096

// ---------------------------------------------------------------------------
// Scratch (device globals — no allocation allowed)
// ---------------------------------------------------------------------------
__device__ float g_q[MROWS * DMODEL];     // Q proj (pre-scaled, tf32-rounded)
__device__ float g_k[MROWS * DMODEL];
__device__ float g_v[MROWS * DMODEL];
__device__ float g_ctx[MROWS * DMODEL];   // attention out (tf32-rounded)
__device__ float r_q[MROWS * DMODEL];     // tf32-rounded inputs
__device__ float r_k[MROWS * DMODEL];
__device__ float r_v[MROWS * DMODEL];
__device__ float r_wq[DMODEL * DMODEL];   // tf32-rounded weights (wq pre-scaled)
__device__ float r_wk[DMODEL * DMODEL];
__device__ float r_wv[DMODEL * DMODEL];
__device__ float r_wo[DMODEL * DMODEL];

__device__ __forceinline__ uint32_t f2tf32(float f) {
    uint32_t u;
    asm("cvt.rna.tf32.f32 %0, %1;" : "=r"(u) : "f"(f));
    return u;
}

// mma.sync m16n8k8 tf32 (layouts validated R4/R5):
//   A: a0=(g,t) a1=(g+8,t) a2=(g,t+4) a3=(g+8,t+4)     [g=lane>>2, t=lane&3]
//   B: b0=(k=t,n=g) b1=(k=t+4,n=g)
//   C: c0=(g,2t) c1=(g,2t+1) c2=(g+8,2t) c3=(g+8,2t+1)
__device__ __forceinline__ void mma_tf32(float* d, const uint32_t* a, const uint32_t* b) {
    asm volatile(
        "mma.sync.aligned.m16n8k8.row.col.f32.tf32.tf32.f32 "
        "{%0,%1,%2,%3}, {%4,%5,%6,%7}, {%8,%9}, {%0,%1,%2,%3};"
        : "+f"(d[0]), "+f"(d[1]), "+f"(d[2]), "+f"(d[3])
        : "r"(a[0]), "r"(a[1]), "r"(a[2]), "r"(a[3]),
          "r"(b[0]), "r"(b[1]));
}

// Fast exp2 for x <= 0, deg-4 minimax + exponent injection (9 ops, no MUFU).
__device__ __forceinline__ float fexp2(float x) {
    x = fmaxf(x, -126.0f);
    float tt = __fadd_rn(x, 12582912.0f);      // 1.5 * 2^23
    float f  = __fsub_rn(x, __fsub_rn(tt, 12582912.0f));
    float p = 9.6859e-3f;
    p = fmaf(p, f, 5.550411e-2f);
    p = fmaf(p, f, 2.4022651e-1f);
    p = fmaf(p, f, 6.9314718e-1f);
    p = fmaf(p, f, 1.0f);
    return __int_as_float(__float_as_int(p) + (__float_as_int(tt) << 23));
}

// cp.async 16B: global -> shared, bypassing registers.
__device__ __forceinline__ void cp_async16(uint32_t dst_smem, const void* src) {
    asm volatile("cp.async.cg.shared.global [%0], [%1], 16;"
                 :: "r"(dst_smem), "l"(src) : "memory");
}
#define CP_COMMIT() asm volatile("cp.async.commit_group;" ::: "memory")
#define CP_WAIT0()  asm volatile("cp.async.wait_group 0;"  ::: "memory")
#define CP_WAIT1()  asm volatile("cp.async.wait_group 1;"  ::: "memory")

// ---------------------------------------------------------------------------
// Prepass: tf32-round inputs & weights (2 batched launches).
// ---------------------------------------------------------------------------
__global__ void round_acts(const float* __restrict__ q, const float* __restrict__ k,
                           const float* __restrict__ v,
                           float* __restrict__ rq, float* __restrict__ rk,
                           float* __restrict__ rv) {
    const int i = blockIdx.x * 256 + threadIdx.x;
    const float* s;
    float* d;
    if (blockIdx.y == 0)      { s = q; d = rq; }
    else if (blockIdx.y == 1) { s = k; d = rk; }
    else                      { s = v; d = rv; }
    float4 x = ((const float4*)s)[i];
    ((uint4*)d)[i] = make_uint4(f2tf32(x.x), f2tf32(x.y), f2tf32(x.z), f2tf32(x.w));
}

__global__ void round_wts(const float* __restrict__ wq, const float* __restrict__ wk,
                          const float* __restrict__ wv, const float* __restrict__ wo,
                          float* __restrict__ rwq, float* __restrict__ rwk,
                          float* __restrict__ rwv, float* __restrict__ rwo,
                          float qscale) {
    const int i = blockIdx.x * 256 + threadIdx.x;
    const float* s;
    float* d;
    float sc = 1.0f;
    if (blockIdx.y == 0)      { s = wq; d = rwq; sc = qscale; }
    else if (blockIdx.y == 1) { s = wk; d = rwk; }
    else if (blockIdx.y == 2) { s = wv; d = rwv; }
    else                      { s = wo; d = rwo; }
    float4 x = ((const float4*)s)[i];
    ((uint4*)d)[i] = make_uint4(f2tf32(x.x * sc), f2tf32(x.y * sc),
                                f2tf32(x.z * sc), f2tf32(x.w * sc));
}

// ---------------------------------------------------------------------------
// GEMM (mma.sync tf32): C = A[M,K] @ W[N,K]^T + bscale*bias.  (R12, proven)
// 128 thr, warp tile 64x64, 3-stage cp.async, one barrier per k-tile.
// ---------------------------------------------------------------------------
#define GBK  16
#define RSTR 20
#define STAGE_F (128 * RSTR)                 // 2560 floats per operand
#define GEMM_SMEM (3 * 2 * STAGE_F * 4)      // 61440 bytes
#define NKT  (DMODEL / GBK)                  // 64

template <bool RoundOut>
__device__ __forceinline__ void gemm_body(const float* __restrict__ A,
                                          const float* __restrict__ W,
                                          const float* __restrict__ bias,
                                          float* __restrict__ C,
                                          float bscale) {
    extern __shared__ uint32_t sg[];

    const int tid  = threadIdx.x;           // 0..127
    const int lane = tid & 31;
    const int wid  = tid >> 5;              // 0..3
    const int g    = lane >> 2;
    const int t    = lane & 3;
    const int wr   = wid >> 1;              // 0..1
    const int wc   = wid & 1;               // 0..1
    const int bx   = blockIdx.x;
    const int by   = blockIdx.y;

    const int lr = tid >> 1;                // 0..63
    const int lc = (tid & 1) * 8;           // 0 or 8
    const float* Ag = A + (size_t)(by * 128 + lr) * DMODEL + lc;
    const float* Wg = W + (size_t)(bx * 128 + lr) * DMODEL + lc;

    const uint32_t sb = (uint32_t)__cvta_generic_to_shared(sg);
    const uint32_t dA0 = sb + (lr * RSTR + lc) * 4;
    const uint32_t dA1 = sb + ((lr + 64) * RSTR + lc) * 4;
    const uint32_t dB0 = dA0 + STAGE_F * 4;
    const uint32_t dB1 = dA1 + STAGE_F * 4;

    #define STAGE_ISSUE(tile, s) do {                                       \
        const float* _a = Ag + (tile) * GBK;                                \
        const float* _w = Wg + (tile) * GBK;                                \
        const uint32_t _o = (uint32_t)(s) * (2 * STAGE_F * 4);              \
        cp_async16(dA0 + _o,      _a);                                      \
        cp_async16(dA0 + _o + 16, _a + 4);                                  \
        cp_async16(dA1 + _o,      _a + 64 * DMODEL);                        \
        cp_async16(dA1 + _o + 16, _a + 64 * DMODEL + 4);                    \
        cp_async16(dB0 + _o,      _w);                                      \
        cp_async16(dB0 + _o + 16, _w + 4);                                  \
        cp_async16(dB1 + _o,      _w + 64 * DMODEL);                        \
        cp_async16(dB1 + _o + 16, _w + 64 * DMODEL + 4);                    \
    } while (0)

    float acc[4][8][4];
    #pragma unroll
    for (int mi = 0; mi < 4; mi++)
        #pragma unroll
        for (int ni = 0; ni < 8; ni++)
            #pragma unroll
            for (int r = 0; r < 4; r++) acc[mi][ni][r] = 0.0f;

    STAGE_ISSUE(0, 0); CP_COMMIT();
    STAGE_ISSUE(1, 1); CP_COMMIT();

    int stg = 0;
    for (int it = 0; it < NKT; it++) {
        CP_WAIT1();
        __syncthreads();

        if (it + 2 < NKT) {
            int s2 = stg + 2; if (s2 >= 3) s2 -= 3;
            STAGE_ISSUE(it + 2, s2);
        }
        CP_COMMIT();

        const uint32_t* As = sg + stg * (2 * STAGE_F);
        const uint32_t* Bs = As + STAGE_F;

        #pragma unroll
        for (int ks = 0; ks < GBK; ks += 8) {
            uint32_t afr[4][4];
            #pragma unroll
            for (int mi = 0; mi < 4; mi++) {
                const int rb = wr * 64 + mi * 16 + g;
                afr[mi][0] = As[rb * RSTR + ks + t];
                afr[mi][1] = As[(rb + 8) * RSTR + ks + t];
                afr[mi][2] = As[rb * RSTR + ks + t + 4];
                afr[mi][3] = As[(rb + 8) * RSTR + ks + t + 4];
            }
            uint32_t bfr[8][2];
            #pragma unroll
            for (int ni = 0; ni < 8; ni++) {
                const int cb = wc * 64 + ni * 8 + g;
                bfr[ni][0] = Bs[cb * RSTR + ks + t];
                bfr[ni][1] = Bs[cb * RSTR + ks + t + 4];
            }
            #pragma unroll
            for (int mi = 0; mi < 4; mi++)
                #pragma unroll
                for (int ni = 0; ni < 8; ni++)
                    mma_tf32(acc[mi][ni], afr[mi], bfr[ni]);
        }

        if (++stg == 3) stg = 0;
    }
    #undef STAGE_ISSUE

    #pragma unroll
    for (int mi = 0; mi < 4; mi++) {
        const int r0 = by * 128 + wr * 64 + mi * 16 + g;
        #pragma unroll
        for (int ni = 0; ni < 8; ni++) {
            const int cc = bx * 128 + wc * 64 + ni * 8 + 2 * t;
            float2 bv = *(const float2*)(bias + cc);
            const float bsx = bv.x * bscale, bsy = bv.y * bscale;
            float v00 = acc[mi][ni][0] + bsx, v01 = acc[mi][ni][1] + bsy;
            float v10 = acc[mi][ni][2] + bsx, v11 = acc[mi][ni][3] + bsy;
            if (RoundOut) {
                *(uint2*)(C + (size_t)r0 * DMODEL + cc) =
                    make_uint2(f2tf32(v00), f2tf32(v01));
                *(uint2*)(C + (size_t)(r0 + 8) * DMODEL + cc) =
                    make_uint2(f2tf32(v10), f2tf32(v11));
            } else {
                *(float2*)(C + (size_t)r0 * DMODEL + cc)       = make_float2(v00, v01);
                *(float2*)(C + (size_t)(r0 + 8) * DMODEL + cc) = make_float2(v10, v11);
            }
        }
    }
}

__global__ __launch_bounds__(128, 2)
void qkv_gemm(const float* q, const float* k, const float* v,
              const float* wq, const float* wk, const float* wv,
              const float* bq, const float* bk, const float* bv,
              float* oq, float* ok, float* ov, float qscale) {
    const float *A, *W, *B;
    float* C;
    float s;
    if (blockIdx.z == 0)      { A = q; W = wq; B = bq; C = oq; s = qscale; }
    else if (blockIdx.z == 1) { A = k; W = wk; B = bk; C = ok; s = 1.0f; }
    else                      { A = v; W = wv; B = bv; C = ov; s = 1.0f; }
    gemm_body<true>(A, W, B, C, s);
}

__global__ __launch_bounds__(128, 2)
void out_gemm(const float* __restrict__ A, const float* __restrict__ W,
              const float* __restrict__ bias, float* __restrict__ C) {
    gemm_body<false>(A, W, bias, C, 1.0f);
}

// ---------------------------------------------------------------------------
// Flash attention v4: R12 memory pattern (LDS.32 conflict-free loads —
// the R13 LDS.64 permute caused bank conflicts and regressed) + deg-4
// fexp2 + NEW: l accumulated by a virtual all-ones V-column inside the PV
// MMA (lacc rescaled by c like oacc), deleting the per-iter rs reduction
// (16 FADD + 8 SHFL). l read from col 0 (lane t=0) and broadcast once at
// the end.
// ---------------------------------------------------------------------------
#define FQT   128
#define FKT   64
#define QSTR  68
#define KSTR  68
#define VSTR  72
#define SM_Q   0
#define SM_K0  (FQT * QSTR)
#define SM_K1  (SM_K0 + FKT * KSTR)
#define SM_V0  (SM_K1 + FKT * KSTR)
#define SM_V1  (SM_V0 + FKT * VSTR)
#define ATT_SMEM ((SM_V1 + FKT * VSTR) * 4)   // 106496 bytes
#define NFT   (SEQ / FKT)

__global__ __launch_bounds__(256, 2)
void flash_attn_mma(const float* __restrict__ Q,
                    const float* __restrict__ Km,
                    const float* __restrict__ Vm,
                    float* __restrict__ ctx) {
    extern __shared__ uint32_t smf[];
    uint32_t* Qs = smf + SM_Q;

    const int tid  = threadIdx.x;
    const int lane = tid & 31;
    const int wid  = tid >> 5;
    const int g    = lane >> 2;
    const int t    = lane & 3;
    const int qb   = wid * 16;
    const int qt   = blockIdx.x;
    const int bh   = blockIdx.y;
    const int b    = bh >> 4;
    const int h    = bh & 15;

    const uint32_t sbase = (uint32_t)__cvta_generic_to_shared(smf);

    // ---- Load Q tile (scaled+rounded by qkv_gemm) ----
    {
        const int r  = tid >> 1;
        const int c0 = (tid & 1) * 32;
        const float* Qg = Q + (size_t)(b * SEQ + qt * FQT + r) * DMODEL + h * DK + c0;
        #pragma unroll
        for (int j = 0; j < 8; j++)
            *(uint4*)(Qs + r * QSTR + c0 + j * 4) = *(const uint4*)(Qg + j * 4);
    }

    float oacc[8][4];
    #pragma unroll
    for (int ni = 0; ni < 8; ni++)
        #pragma unroll
        for (int r = 0; r < 4; r++) oacc[ni][r] = 0.0f;
    float lacc[4] = {0.0f, 0.0f, 0.0f, 0.0f};   // ones-column accumulator
    float m0 = -1e30f, m1 = -1e30f;

    // B-fragment for the all-ones column (col 0 = 1, cols 1..7 = 0)
    uint32_t bones[2];
    bones[0] = (g == 0) ? 0x3F800000u : 0u;
    bones[1] = bones[0];

    const int kvr = tid >> 2;
    const int kvc = (tid & 3) * 16;
    const float* Kg0 = Km + (size_t)(b * SEQ + kvr) * DMODEL + h * DK + kvc;
    const float* Vg0 = Vm + (size_t)(b * SEQ + kvr) * DMODEL + h * DK + kvc;

    const uint32_t dK0 = sbase + (SM_K0 + kvr * KSTR + kvc) * 4;
    const uint32_t dK1 = sbase + (SM_K1 + kvr * KSTR + kvc) * 4;
    const uint32_t dV0 = sbase + (SM_V0 + kvr * VSTR + kvc) * 4;
    const uint32_t dV1 = sbase + (SM_V1 + kvr * VSTR + kvc) * 4;

    #pragma unroll
    for (int j = 0; j < 4; j++) {
        cp_async16(dK0 + j * 16, Kg0 + j * 4);
        cp_async16(dV0 + j * 16, Vg0 + j * 4);
    }
    CP_COMMIT();

    for (int kt = 0; kt < NFT; kt++) {
        const int buf = kt & 1;
        uint32_t* Ks = smf + SM_K0 + buf * (FKT * KSTR);
        uint32_t* Vs = smf + SM_V0 + buf * (FKT * VSTR);

        CP_WAIT0();
        __syncthreads();

        if (kt + 1 < NFT) {
            const float* Kg = Kg0 + (size_t)(kt + 1) * FKT * DMODEL;
            const float* Vg = Vg0 + (size_t)(kt + 1) * FKT * DMODEL;
            const uint32_t dk = buf ? dK0 : dK1;
            const uint32_t dv = buf ? dV0 : dV1;
            #pragma unroll
            for (int j = 0; j < 4; j++) {
                cp_async16(dk + j * 16, Kg + j * 4);
                cp_async16(dv + j * 16, Vg + j * 4);
            }
            CP_COMMIT();
        }

        // ---- S = Q K^T (log2 domain) ----
        float s[8][4];
        #pragma unroll
        for (int ni = 0; ni < 8; ni++)
            #pragma unroll
            for (int r = 0; r < 4; r++) s[ni][r] = 0.0f;

        #pragma unroll
        for (int ks = 0; ks < 8; ks++) {
            const int kc = ks * 8 + t;
            uint32_t a[4];
            a[0] = Qs[(qb + g    ) * QSTR + kc];
            a[1] = Qs[(qb + g + 8) * QSTR + kc];
            a[2] = Qs[(qb + g    ) * QSTR + kc + 4];
            a[3] = Qs[(qb + g + 8) * QSTR + kc + 4];
            #pragma unroll
            for (int ni = 0; ni < 8; ni++) {
                uint32_t bb[2];
                bb[0] = Ks[(ni * 8 + g) * KSTR + kc];
                bb[1] = Ks[(ni * 8 + g) * KSTR + kc + 4];
                mma_tf32(s[ni], a, bb);
            }
        }

        // ---- Online softmax max (reduce over 4-lane t-group) ----
        float tm0 = -1e30f, tm1 = -1e30f;
        #pragma unroll
        for (int ni = 0; ni < 8; ni++) {
            tm0 = fmaxf(tm0, fmaxf(s[ni][0], s[ni][1]));
            tm1 = fmaxf(tm1, fmaxf(s[ni][2], s[ni][3]));
        }
        tm0 = fmaxf(tm0, __shfl_xor_sync(0xffffffffu, tm0, 1));
        tm0 = fmaxf(tm0, __shfl_xor_sync(0xffffffffu, tm0, 2));
        tm1 = fmaxf(tm1, __shfl_xor_sync(0xffffffffu, tm1, 1));
        tm1 = fmaxf(tm1, __shfl_xor_sync(0xffffffffu, tm1, 2));

        const float mn0 = fmaxf(m0, tm0);
        const float mn1 = fmaxf(m1, tm1);
        const float c0 = fexp2(m0 - mn0);
        const float c1 = fexp2(m1 - mn1);
        m0 = mn0; m1 = mn1;

        uint32_t ps[8][4];
        #pragma unroll
        for (int ni = 0; ni < 8; ni++) {
            ps[ni][0] = f2tf32(fexp2(s[ni][0] - mn0));
            ps[ni][1] = f2tf32(fexp2(s[ni][1] - mn0));
            ps[ni][2] = f2tf32(fexp2(s[ni][2] - mn1));
            ps[ni][3] = f2tf32(fexp2(s[ni][3] - mn1));
        }

        #pragma unroll
        for (int ni = 0; ni < 8; ni++) {
            oacc[ni][0] *= c0; oacc[ni][1] *= c0;
            oacc[ni][2] *= c1; oacc[ni][3] *= c1;
        }
        lacc[0] *= c0; lacc[2] *= c1;

        // ---- O += P V ; l += P 1 (shuffle-transposed P) ----
        const int srcA = (g << 2) | (t >> 1);
        const int srcB = srcA + 2;
        const bool odd = (t & 1) != 0;
        #pragma unroll
        for (int ks = 0; ks < 8; ks++) {
            uint32_t x0 = __shfl_sync(0xffffffffu, ps[ks][0], srcA);
            uint32_t x1 = __shfl_sync(0xffffffffu, ps[ks][1], srcA);
            uint32_t x2 = __shfl_sync(0xffffffffu, ps[ks][2], srcA);
            uint32_t x3 = __shfl_sync(0xffffffffu, ps[ks][3], srcA);
            uint32_t y0 = __shfl_sync(0xffffffffu, ps[ks][0], srcB);
            uint32_t y1 = __shfl_sync(0xffffffffu, ps[ks][1], srcB);
            uint32_t y2 = __shfl_sync(0xffffffffu, ps[ks][2], srcB);
            uint32_t y3 = __shfl_sync(0xffffffffu, ps[ks][3], srcB);
            uint32_t a[4];
            a[0] = odd ? x1 : x0;
            a[1] = odd ? x3 : x2;
            a[2] = odd ? y1 : y0;
            a[3] = odd ? y3 : y2;
            mma_tf32(lacc, a, bones);
            #pragma unroll
            for (int ni = 0; ni < 8; ni++) {
                uint32_t bb[2];
                bb[0] = Vs[(ks * 8 + t    ) * VSTR + ni * 8 + g];
                bb[1] = Vs[(ks * 8 + t + 4) * VSTR + ni * 8 + g];
                mma_tf32(oacc[ni], a, bb);
            }
        }
    }

    // ---- Broadcast l from lane t=0 of each t-group, normalize, write ----
    const int src0 = lane & 0x1C;   // (g<<2) | 0
    const float l0 = __shfl_sync(0xffffffffu, lacc[0], src0);
    const float l1 = __shfl_sync(0xffffffffu, lacc[2], src0);
    const float inv0 = 1.0f / l0;
    const float inv1 = 1.0f / l1;
    const int r0 = b * SEQ + qt * FQT + qb + g;
    #pragma unroll
    for (int ni = 0; ni < 8; ni++) {
        const int cc = h * DK + ni * 8 + 2 * t;
        *(uint2*)(ctx + (size_t)r0 * DMODEL + cc) =
            make_uint2(f2tf32(oacc[ni][0] * inv0), f2tf32(oacc[ni][1] * inv0));
        *(uint2*)(ctx + (size_t)(r0 + 8) * DMODEL + cc) =
            make_uint2(f2tf32(oacc[ni][2] * inv1), f2tf32(oacc[ni][3] * inv1));
    }
}

// ---------------------------------------------------------------------------
// Launch
// ---------------------------------------------------------------------------
extern "C" void kernel_launch(void* const* d_in, const int* in_sizes, int n_in,
                              void* d_out, int out_size) {
    const float* q   = (const float*)d_in[0];
    const float* k   = (const float*)d_in[1];
    const float* v   = (const float*)d_in[2];
    const float* w_q = (const float*)d_in[3];
    const float* w_k = (const float*)d_in[4];
    const float* w_v = (const float*)d_in[5];
    const float* w_o = (const float*)d_in[6];
    const float* b_q = (const float*)d_in[7];
    const float* b_k = (const float*)d_in[8];
    const float* b_v = (const float*)d_in[9];
    const float* b_o = (const float*)d_in[10];
    float* out = (float*)d_out;

    float *gq, *gk, *gv, *gctx;
    float *rq, *rk, *rv, *rwq, *rwk, *rwv, *rwo;
    cudaGetSymbolAddress((void**)&gq,   g_q);
    cudaGetSymbolAddress((void**)&gk,   g_k);
    cudaGetSymbolAddress((void**)&gv,   g_v);
    cudaGetSymbolAddress((void**)&gctx, g_ctx);
    cudaGetSymbolAddress((void**)&rq,   r_q);
    cudaGetSymbolAddress((void**)&rk,   r_k);
    cudaGetSymbolAddress((void**)&rv,   r_v);
    cudaGetSymbolAddress((void**)&rwq,  r_wq);
    cudaGetSymbolAddress((void**)&rwk,  r_wk);
    cudaGetSymbolAddress((void**)&rwv,  r_wv);
    cudaGetSymbolAddress((void**)&rwo,  r_wo);

    cudaFuncSetAttribute(flash_attn_mma, cudaFuncAttributeMaxDynamicSharedMemorySize, ATT_SMEM);
    cudaFuncSetAttribute(qkv_gemm, cudaFuncAttributeMaxDynamicSharedMemorySize, GEMM_SMEM);
    cudaFuncSetAttribute(out_gemm, cudaFuncAttributeMaxDynamicSharedMemorySize, GEMM_SMEM);

    const float SCLL2E = 0.125f * 1.44269504088896f;

    dim3 ga(MROWS * DMODEL / 4 / 256, 3);   // (4096, 3)
    round_acts<<<ga, 256>>>(q, k, v, rq, rk, rv);
    dim3 gw(DMODEL * DMODEL / 4 / 256, 4);  // (1024, 4)
    round_wts<<<gw, 256>>>(w_q, w_k, w_v, w_o, rwq, rwk, rwv, rwo, SCLL2E);

    dim3 gqkv(DMODEL / 128, MROWS / 128, 3);  // (8, 32, 3)
    qkv_gemm<<<gqkv, 128, GEMM_SMEM>>>(rq, rk, rv, rwq, rwk, rwv,
                                       b_q, b_k, b_v, gq, gk, gv, SCLL2E);

    dim3 ag(SEQ / FQT, BATCH * NHEADS);       // (16, 32)
    flash_attn_mma<<<ag, 256, ATT_SMEM>>>(gq, gk, gv, gctx);

    dim3 gg(DMODEL / 128, MROWS / 128);       // (8, 32)
    out_gemm<<<gg, 128, GEMM_SMEM>>>(gctx, rwo, b_o, out);
}